// round 2
// baseline (speedup 1.0000x reference)
#include <cuda_runtime.h>
#include <math.h>

// Problem constants
#define N_TOK  2048   // B*S
#define SEQ    1024
#define BATCH  2
#define DMODEL 2048
#define KVD    1024
#define FFDIM  8192
#define NLAYER 4
#define NH     16
#define NKV    8
#define HD     128
#define VOCAB  32000

// ---------------- scratch (device globals; no allocation allowed) ----------
__device__ float g_x   [N_TOK * DMODEL];
__device__ float g_xn  [N_TOK * DMODEL];
__device__ float g_q   [N_TOK * DMODEL];
__device__ float g_k   [N_TOK * KVD];
__device__ float g_v   [N_TOK * KVD];
__device__ float g_attn[N_TOK * DMODEL];
__device__ float g_gate[N_TOK * FFDIM];
__device__ float g_up  [N_TOK * FFDIM];
__device__ float g_cos [SEQ * 64];
__device__ float g_sin [SEQ * 64];

// ---------------- embedding gather ----------------
__global__ void embed_kernel(const int* __restrict__ ids,
                             const float* __restrict__ embed,
                             float* __restrict__ out) {
    int i4 = blockIdx.x * blockDim.x + threadIdx.x;      // over N_TOK * DMODEL/4
    if (i4 >= N_TOK * (DMODEL / 4)) return;
    int tok  = i4 >> 9;            // /(DMODEL/4)=512
    int col4 = i4 & 511;
    int id = ids[tok];
    ((float4*)out)[i4] = ((const float4*)(embed + (size_t)id * DMODEL))[col4];
}

// ---------------- RoPE tables (double precision, matches jax within fp32 noise) ----
__global__ void rope_table_kernel(float* __restrict__ ctab, float* __restrict__ stab) {
    int i = blockIdx.x * blockDim.x + threadIdx.x;       // SEQ*64
    if (i >= SEQ * 64) return;
    int s  = i >> 6;
    int fi = i & 63;
    double freq = exp(-(double)fi * (log(10000.0) / 64.0));
    double a = (double)s * freq;
    ctab[i] = (float)cos(a);
    stab[i] = (float)sin(a);
}

// ---------------- RoPE apply (in-place on q or k) ----------------
__global__ void rope_apply_kernel(float* __restrict__ x, int heads,
                                  const float* __restrict__ ctab,
                                  const float* __restrict__ stab) {
    int i = blockIdx.x * blockDim.x + threadIdx.x;       // N_TOK*heads*64
    if (i >= N_TOK * heads * 64) return;
    int fi = i & 63;
    int h  = (i >> 6) % heads;
    int t  = i / (64 * heads);
    int s  = t & (SEQ - 1);
    float c  = ctab[s * 64 + fi];
    float sn = stab[s * 64 + fi];
    float* p = x + (size_t)t * (heads * HD) + h * HD + fi;
    float x1 = p[0], x2 = p[64];
    p[0]  = x1 * c  - x2 * sn;
    p[64] = x1 * sn + x2 * c;
}

// ---------------- RMSNorm (one block per row) ----------------
__global__ __launch_bounds__(256) void rmsnorm_kernel(const float* __restrict__ x,
                                                      const float* __restrict__ w,
                                                      float* __restrict__ o) {
    int row = blockIdx.x;
    int t = threadIdx.x;
    const float4* xr = (const float4*)(x + (size_t)row * DMODEL);
    float4 v0 = xr[t];
    float4 v1 = xr[t + 256];
    float ss = v0.x*v0.x + v0.y*v0.y + v0.z*v0.z + v0.w*v0.w
             + v1.x*v1.x + v1.y*v1.y + v1.z*v1.z + v1.w*v1.w;
    #pragma unroll
    for (int off = 16; off; off >>= 1) ss += __shfl_xor_sync(0xffffffffu, ss, off);
    __shared__ float red[8];
    if ((t & 31) == 0) red[t >> 5] = ss;
    __syncthreads();
    float tot = red[0] + red[1] + red[2] + red[3] + red[4] + red[5] + red[6] + red[7];
    float inv = rsqrtf(tot * (1.0f / DMODEL) + 1e-6f);
    const float4* wr = (const float4*)w;
    float4* orow = (float4*)(o + (size_t)row * DMODEL);
    float4 w0 = wr[t], w1 = wr[t + 256];
    float4 r0, r1;
    r0.x = v0.x * inv * w0.x; r0.y = v0.y * inv * w0.y;
    r0.z = v0.z * inv * w0.z; r0.w = v0.w * inv * w0.w;
    r1.x = v1.x * inv * w1.x; r1.y = v1.y * inv * w1.y;
    r1.z = v1.z * inv * w1.z; r1.w = v1.w * inv * w1.w;
    orow[t] = r0;
    orow[t + 256] = r1;
}

// ---------------- SGEMM: C[N,M] = A[N,K] * W[M,K]^T (+ residual) ----------------
// 128x128 block, BK=16, 256 threads, 8x8 per-thread microtile.
// Register double-buffer: prefetch next K-tile from global while computing
// current tile out of (single-buffered) shared memory.
// All shapes guaranteed divisible: N%128==0, M%128==0, K%16==0.
__global__ __launch_bounds__(256) void gemm_tn(const float* __restrict__ A,
                                               const float* __restrict__ W,
                                               float* __restrict__ C,
                                               const float* __restrict__ res,
                                               int M, int K) {
    __shared__ float As[16][132];
    __shared__ float Ws[16][132];
    const int tid = threadIdx.x;
    const int n0 = blockIdx.y * 128;
    const int m0 = blockIdx.x * 128;
    const int ty = tid >> 4;       // 0..15
    const int tx = tid & 15;       // 0..15

    // global-load mapping: thread covers rows r0 and r0+64, same 4-col group
    const int r0 = tid >> 2;           // 0..63
    const int c4 = (tid & 3) << 2;     // 0,4,8,12

    float acc[8][8];
    #pragma unroll
    for (int i = 0; i < 8; i++)
        #pragma unroll
        for (int j = 0; j < 8; j++) acc[i][j] = 0.f;

    const float* Ab = A + (size_t)n0 * K;
    const float* Wb = W + (size_t)m0 * K;

    float4 ra0, ra1, rw0, rw1;

    // prologue: load first tile
    {
        const float* pa = Ab + (size_t)r0 * K + c4;
        const float* pw = Wb + (size_t)r0 * K + c4;
        ra0 = *(const float4*)pa;
        ra1 = *(const float4*)(pa + (size_t)64 * K);
        rw0 = *(const float4*)pw;
        rw1 = *(const float4*)(pw + (size_t)64 * K);
    }

    for (int k0 = 0; k0 < K; k0 += 16) {
        // store prefetched tile to smem (transposed: [k][row])
        As[c4    ][r0] = ra0.x; As[c4 + 1][r0] = ra0.y;
        As[c4 + 2][r0] = ra0.z; As[c4 + 3][r0] = ra0.w;
        As[c4    ][r0 + 64] = ra1.x; As[c4 + 1][r0 + 64] = ra1.y;
        As[c4 + 2][r0 + 64] = ra1.z; As[c4 + 3][r0 + 64] = ra1.w;
        Ws[c4    ][r0] = rw0.x; Ws[c4 + 1][r0] = rw0.y;
        Ws[c4 + 2][r0] = rw0.z; Ws[c4 + 3][r0] = rw0.w;
        Ws[c4    ][r0 + 64] = rw1.x; Ws[c4 + 1][r0 + 64] = rw1.y;
        Ws[c4 + 2][r0 + 64] = rw1.z; Ws[c4 + 3][r0 + 64] = rw1.w;
        __syncthreads();

        // prefetch next tile from global while computing this one
        if (k0 + 16 < K) {
            const float* pa = Ab + (size_t)r0 * K + k0 + 16 + c4;
            const float* pw = Wb + (size_t)r0 * K + k0 + 16 + c4;
            ra0 = *(const float4*)pa;
            ra1 = *(const float4*)(pa + (size_t)64 * K);
            rw0 = *(const float4*)pw;
            rw1 = *(const float4*)(pw + (size_t)64 * K);
        }

        #pragma unroll
        for (int kk = 0; kk < 16; kk++) {
            float4 a0 = *(const float4*)&As[kk][ty * 8];
            float4 a1 = *(const float4*)&As[kk][ty * 8 + 4];
            float4 b0 = *(const float4*)&Ws[kk][tx * 8];
            float4 b1 = *(const float4*)&Ws[kk][tx * 8 + 4];
            float ar[8] = {a0.x, a0.y, a0.z, a0.w, a1.x, a1.y, a1.z, a1.w};
            float br[8] = {b0.x, b0.y, b0.z, b0.w, b1.x, b1.y, b1.z, b1.w};
            #pragma unroll
            for (int i = 0; i < 8; i++)
                #pragma unroll
                for (int j = 0; j < 8; j++)
                    acc[i][j] += ar[i] * br[j];
        }
        __syncthreads();
    }

    #pragma unroll
    for (int i = 0; i < 8; i++) {
        size_t off = (size_t)(n0 + ty * 8 + i) * M + m0 + tx * 8;
        float4 c0 = make_float4(acc[i][0], acc[i][1], acc[i][2], acc[i][3]);
        float4 c1 = make_float4(acc[i][4], acc[i][5], acc[i][6], acc[i][7]);
        if (res) {
            float4 r0v = *(const float4*)(res + off);
            float4 r1v = *(const float4*)(res + off + 4);
            c0.x += r0v.x; c0.y += r0v.y; c0.z += r0v.z; c0.w += r0v.w;
            c1.x += r1v.x; c1.y += r1v.y; c1.z += r1v.z; c1.w += r1v.w;
        }
        *(float4*)(C + off)     = c0;
        *(float4*)(C + off + 4) = c1;
    }
}

// ---------------- causal attention, online softmax, 4 queries per warp ----------
#define QPW 4
__global__ __launch_bounds__(256) void attn_kernel(const float* __restrict__ q,
                                                   const float* __restrict__ k,
                                                   const float* __restrict__ v,
                                                   float* __restrict__ out) {
    int gwarp = (blockIdx.x * blockDim.x + threadIdx.x) >> 5;  // B*NH*(SEQ/QPW) = 8192
    int lane = threadIdx.x & 31;
    int qg = gwarp & 255;         // SEQ/QPW = 256
    int bh = gwarp >> 8;          // 0..31
    int b = bh >> 4;
    int h = bh & 15;
    int kvh = h >> 1;             // GQA group = 2
    int q0 = qg * QPW;

    const float scale = 0.08838834764831845f;  // 1/sqrt(128)

    float4 qv[QPW];
    float  m[QPW], l[QPW];
    float4 acc[QPW];
    #pragma unroll
    for (int r = 0; r < QPW; r++) {
        qv[r] = *(const float4*)&q[(size_t)(b * SEQ + q0 + r) * DMODEL + h * HD + lane * 4];
        m[r] = -1e30f;
        l[r] = 0.f;
        acc[r] = make_float4(0.f, 0.f, 0.f, 0.f);
    }

    const float* kbase = k + (size_t)b * SEQ * KVD + kvh * HD + lane * 4;
    const float* vbase = v + (size_t)b * SEQ * KVD + kvh * HD + lane * 4;
    int jmax = q0 + QPW - 1;

    for (int j = 0; j <= jmax; j++) {
        float4 kv4 = *(const float4*)(kbase + (size_t)j * KVD);
        float d[QPW];
        #pragma unroll
        for (int r = 0; r < QPW; r++)
            d[r] = qv[r].x * kv4.x + qv[r].y * kv4.y + qv[r].z * kv4.z + qv[r].w * kv4.w;
        #pragma unroll
        for (int off = 16; off; off >>= 1) {
            #pragma unroll
            for (int r = 0; r < QPW; r++)
                d[r] += __shfl_xor_sync(0xffffffffu, d[r], off);
        }
        float4 vv = *(const float4*)(vbase + (size_t)j * KVD);
        #pragma unroll
        for (int r = 0; r < QPW; r++) {
            if (j <= q0 + r) {
                float dr = d[r] * scale;
                float mn = fmaxf(m[r], dr);
                float corr = __expf(m[r] - mn);
                float p = __expf(dr - mn);
                l[r] = l[r] * corr + p;
                acc[r].x = acc[r].x * corr + p * vv.x;
                acc[r].y = acc[r].y * corr + p * vv.y;
                acc[r].z = acc[r].z * corr + p * vv.z;
                acc[r].w = acc[r].w * corr + p * vv.w;
                m[r] = mn;
            }
        }
    }

    #pragma unroll
    for (int r = 0; r < QPW; r++) {
        float inv = 1.f / l[r];
        float4 o = make_float4(acc[r].x * inv, acc[r].y * inv, acc[r].z * inv, acc[r].w * inv);
        *(float4*)&out[(size_t)(b * SEQ + q0 + r) * DMODEL + h * HD + lane * 4] = o;
    }
}

// ---------------- gate = silu(gate) * up ----------------
__global__ void silu_mul_kernel(float* __restrict__ gate, const float* __restrict__ up) {
    int i4 = blockIdx.x * blockDim.x + threadIdx.x;      // N_TOK*FFDIM/4
    if (i4 >= N_TOK * (FFDIM / 4)) return;
    float4 g = ((float4*)gate)[i4];
    float4 u = ((const float4*)up)[i4];
    g.x = g.x / (1.f + expf(-g.x)) * u.x;
    g.y = g.y / (1.f + expf(-g.y)) * u.y;
    g.z = g.z / (1.f + expf(-g.z)) * u.z;
    g.w = g.w / (1.f + expf(-g.w)) * u.w;
    ((float4*)gate)[i4] = g;
}

// ---------------- host-side orchestration ----------------
static void* sym(const void* devsym) {
    void* p = nullptr;
    cudaGetSymbolAddress(&p, devsym);
    return p;
}

extern "C" void kernel_launch(void* const* d_in, const int* in_sizes, int n_in,
                              void* d_out, int out_size) {
    // Input layout: ids, [num_heads, num_kv_heads,] embed, ln1, wq, wk, wv, wo,
    //               ln2, wg, wu, wd, norm_w, lm_head
    int e = 1;
    if (n_in >= 15) e = 3;   // scalar num_heads/num_kv_heads present
    const int*   ids   = (const int*)d_in[0];
    const float* embed = (const float*)d_in[e + 0];
    const float* ln1   = (const float*)d_in[e + 1];
    const float* wq    = (const float*)d_in[e + 2];
    const float* wk    = (const float*)d_in[e + 3];
    const float* wv    = (const float*)d_in[e + 4];
    const float* wo    = (const float*)d_in[e + 5];
    const float* ln2   = (const float*)d_in[e + 6];
    const float* wg    = (const float*)d_in[e + 7];
    const float* wu    = (const float*)d_in[e + 8];
    const float* wd    = (const float*)d_in[e + 9];
    const float* nw    = (const float*)d_in[e + 10];
    const float* lmh   = (const float*)d_in[e + 11];
    float* out = (float*)d_out;

    float* x    = (float*)sym(g_x);
    float* xn   = (float*)sym(g_xn);
    float* q    = (float*)sym(g_q);
    float* kbuf = (float*)sym(g_k);
    float* vbuf = (float*)sym(g_v);
    float* attn = (float*)sym(g_attn);
    float* gate = (float*)sym(g_gate);
    float* up   = (float*)sym(g_up);
    float* ctab = (float*)sym(g_cos);
    float* stab = (float*)sym(g_sin);

    dim3 blk(256);

    // embedding
    embed_kernel<<<(N_TOK * DMODEL / 4 + 255) / 256, blk>>>(ids, embed, x);
    // rope tables
    rope_table_kernel<<<(SEQ * 64 + 255) / 256, blk>>>(ctab, stab);

    for (int L = 0; L < NLAYER; L++) {
        const float* l1w = ln1 + (size_t)L * DMODEL;
        const float* l2w = ln2 + (size_t)L * DMODEL;
        const float* qw  = wq + (size_t)L * DMODEL * DMODEL;
        const float* kw  = wk + (size_t)L * KVD * DMODEL;
        const float* vw  = wv + (size_t)L * KVD * DMODEL;
        const float* ow  = wo + (size_t)L * DMODEL * DMODEL;
        const float* gw  = wg + (size_t)L * FFDIM * DMODEL;
        const float* uw  = wu + (size_t)L * FFDIM * DMODEL;
        const float* dw  = wd + (size_t)L * DMODEL * FFDIM;

        // attn block
        rmsnorm_kernel<<<N_TOK, blk>>>(x, l1w, xn);
        gemm_tn<<<dim3(DMODEL / 128, N_TOK / 128), blk>>>(xn, qw, q,    nullptr, DMODEL, DMODEL);
        gemm_tn<<<dim3(KVD    / 128, N_TOK / 128), blk>>>(xn, kw, kbuf, nullptr, KVD,    DMODEL);
        gemm_tn<<<dim3(KVD    / 128, N_TOK / 128), blk>>>(xn, vw, vbuf, nullptr, KVD,    DMODEL);
        rope_apply_kernel<<<(N_TOK * NH  * 64 + 255) / 256, blk>>>(q,    NH,  ctab, stab);
        rope_apply_kernel<<<(N_TOK * NKV * 64 + 255) / 256, blk>>>(kbuf, NKV, ctab, stab);
        attn_kernel<<<(BATCH * NH * (SEQ / QPW)) * 32 / 256, blk>>>(q, kbuf, vbuf, attn);
        gemm_tn<<<dim3(DMODEL / 128, N_TOK / 128), blk>>>(attn, ow, x, x, DMODEL, DMODEL);

        // ffn block
        rmsnorm_kernel<<<N_TOK, blk>>>(x, l2w, xn);
        gemm_tn<<<dim3(FFDIM / 128, N_TOK / 128), blk>>>(xn, gw, gate, nullptr, FFDIM, DMODEL);
        gemm_tn<<<dim3(FFDIM / 128, N_TOK / 128), blk>>>(xn, uw, up,   nullptr, FFDIM, DMODEL);
        silu_mul_kernel<<<(N_TOK * FFDIM / 4 + 255) / 256, blk>>>(gate, up);
        gemm_tn<<<dim3(DMODEL / 128, N_TOK / 128), blk>>>(gate, dw, x, x, DMODEL, FFDIM);
    }

    // final norm + lm_head
    rmsnorm_kernel<<<N_TOK, blk>>>(x, nw, xn);
    gemm_tn<<<dim3(VOCAB / 128, N_TOK / 128), blk>>>(xn, lmh, out, nullptr, VOCAB, DMODEL);
}

// round 5
// speedup vs baseline: 2.5316x; 2.5316x over previous
#include <cuda_runtime.h>
#include <cuda_bf16.h>
#include <math.h>
#include <stdint.h>

// Problem constants
#define N_TOK  2048   // B*S
#define SEQ    1024
#define BATCH  2
#define DMODEL 2048
#define KVD    1024
#define FFDIM  8192
#define NLAYER 4
#define NH     16
#define NKV    8
#define HD     128
#define VOCAB  32000

// GEMM tiling (mma.sync path; tcgen05 unavailable: harness PTX targets compute_103)
#define BN 128
#define BM 128
#define BK 64
#define TILE_BYTES 16384          // 128 rows x 64 bf16 x 2B
#define STAGE_BYTES (4 * TILE_BYTES)   // Ahi, Alo, Whi, Wlo
#define GEMM_SMEM (2 * STAGE_BYTES + 1024)

#define SWZ(off) ((off) ^ (((off) >> 3) & 0x70))

// ---------------- scratch (device globals; no allocation allowed) ----------
__device__ float g_x   [N_TOK * DMODEL];
__device__ float g_q   [N_TOK * DMODEL];
__device__ float g_k   [N_TOK * KVD];
__device__ float g_v   [N_TOK * KVD];
__device__ float g_attn[N_TOK * DMODEL];
__device__ float g_gate[N_TOK * FFDIM];
__device__ float g_up  [N_TOK * FFDIM];
__device__ float g_cos [SEQ * 64];
__device__ float g_sin [SEQ * 64];

// bf16 hi/lo activations
__device__ __align__(128) __nv_bfloat16 g_xn_h [N_TOK * DMODEL];
__device__ __align__(128) __nv_bfloat16 g_xn_l [N_TOK * DMODEL];
__device__ __align__(128) __nv_bfloat16 g_at_h [N_TOK * DMODEL];
__device__ __align__(128) __nv_bfloat16 g_at_l [N_TOK * DMODEL];
__device__ __align__(128) __nv_bfloat16 g_gl_h [N_TOK * FFDIM];
__device__ __align__(128) __nv_bfloat16 g_gl_l [N_TOK * FFDIM];

// bf16 hi/lo weights
__device__ __align__(128) __nv_bfloat16 g_wq_h[NLAYER * DMODEL * DMODEL];
__device__ __align__(128) __nv_bfloat16 g_wq_l[NLAYER * DMODEL * DMODEL];
__device__ __align__(128) __nv_bfloat16 g_wk_h[NLAYER * KVD * DMODEL];
__device__ __align__(128) __nv_bfloat16 g_wk_l[NLAYER * KVD * DMODEL];
__device__ __align__(128) __nv_bfloat16 g_wv_h[NLAYER * KVD * DMODEL];
__device__ __align__(128) __nv_bfloat16 g_wv_l[NLAYER * KVD * DMODEL];
__device__ __align__(128) __nv_bfloat16 g_wo_h[NLAYER * DMODEL * DMODEL];
__device__ __align__(128) __nv_bfloat16 g_wo_l[NLAYER * DMODEL * DMODEL];
__device__ __align__(128) __nv_bfloat16 g_wg_h[NLAYER * FFDIM * DMODEL];
__device__ __align__(128) __nv_bfloat16 g_wg_l[NLAYER * FFDIM * DMODEL];
__device__ __align__(128) __nv_bfloat16 g_wu_h[NLAYER * FFDIM * DMODEL];
__device__ __align__(128) __nv_bfloat16 g_wu_l[NLAYER * FFDIM * DMODEL];
__device__ __align__(128) __nv_bfloat16 g_wd_h[NLAYER * DMODEL * FFDIM];
__device__ __align__(128) __nv_bfloat16 g_wd_l[NLAYER * DMODEL * FFDIM];
__device__ __align__(128) __nv_bfloat16 g_lm_h[VOCAB * DMODEL];
__device__ __align__(128) __nv_bfloat16 g_lm_l[VOCAB * DMODEL];

// ---------------- PTX helpers (base ISA only) ----------------
__device__ __forceinline__ uint32_t smem_u32(const void* p) {
    uint32_t a;
    asm("{ .reg .u64 t; cvta.to.shared.u64 t, %1; cvt.u32.u64 %0, t; }" : "=r"(a) : "l"(p));
    return a;
}

__device__ __forceinline__ void cp16(uint32_t s, const void* g) {
    asm volatile("cp.async.cg.shared.global [%0], [%1], 16;" :: "r"(s), "l"(g));
}

__device__ __forceinline__ void ldm_x4(uint32_t* d, uint32_t addr) {
    asm volatile("ldmatrix.sync.aligned.m8n8.x4.shared.b16 {%0,%1,%2,%3}, [%4];"
        : "=r"(d[0]), "=r"(d[1]), "=r"(d[2]), "=r"(d[3]) : "r"(addr));
}

__device__ __forceinline__ void mma_bf16(float* c, uint32_t a0, uint32_t a1,
                                         uint32_t a2, uint32_t a3,
                                         uint32_t b0, uint32_t b1) {
    asm volatile("mma.sync.aligned.m16n8k16.row.col.f32.bf16.bf16.f32 "
        "{%0,%1,%2,%3}, {%4,%5,%6,%7}, {%8,%9}, {%0,%1,%2,%3};"
        : "+f"(c[0]), "+f"(c[1]), "+f"(c[2]), "+f"(c[3])
        : "r"(a0), "r"(a1), "r"(a2), "r"(a3), "r"(b0), "r"(b1));
}

// ---------------- embedding gather ----------------
__global__ void embed_kernel(const int* __restrict__ ids,
                             const float* __restrict__ embed,
                             float* __restrict__ out) {
    int i4 = blockIdx.x * blockDim.x + threadIdx.x;
    if (i4 >= N_TOK * (DMODEL / 4)) return;
    int tok  = i4 >> 9;
    int col4 = i4 & 511;
    int id = ids[tok];
    ((float4*)out)[i4] = ((const float4*)(embed + (size_t)id * DMODEL))[col4];
}

// ---------------- fp32 -> bf16 hi/lo conversion ----------------
__global__ void cvt_kernel(const float* __restrict__ src,
                           __nv_bfloat16* __restrict__ hi,
                           __nv_bfloat16* __restrict__ lo, int n4) {
    int i4 = blockIdx.x * blockDim.x + threadIdx.x;
    if (i4 >= n4) return;
    float4 v = ((const float4*)src)[i4];
    __nv_bfloat16 h0 = __float2bfloat16_rn(v.x), h1 = __float2bfloat16_rn(v.y);
    __nv_bfloat16 h2 = __float2bfloat16_rn(v.z), h3 = __float2bfloat16_rn(v.w);
    __nv_bfloat16 l0 = __float2bfloat16_rn(v.x - __bfloat162float(h0));
    __nv_bfloat16 l1 = __float2bfloat16_rn(v.y - __bfloat162float(h1));
    __nv_bfloat16 l2 = __float2bfloat16_rn(v.z - __bfloat162float(h2));
    __nv_bfloat16 l3 = __float2bfloat16_rn(v.w - __bfloat162float(h3));
    ((__nv_bfloat162*)hi)[i4 * 2]     = __nv_bfloat162(h0, h1);
    ((__nv_bfloat162*)hi)[i4 * 2 + 1] = __nv_bfloat162(h2, h3);
    ((__nv_bfloat162*)lo)[i4 * 2]     = __nv_bfloat162(l0, l1);
    ((__nv_bfloat162*)lo)[i4 * 2 + 1] = __nv_bfloat162(l2, l3);
}

// ---------------- RoPE tables ----------------
__global__ void rope_table_kernel(float* __restrict__ ctab, float* __restrict__ stab) {
    int i = blockIdx.x * blockDim.x + threadIdx.x;
    if (i >= SEQ * 64) return;
    int s  = i >> 6;
    int fi = i & 63;
    double freq = exp(-(double)fi * (log(10000.0) / 64.0));
    double a = (double)s * freq;
    ctab[i] = (float)cos(a);
    stab[i] = (float)sin(a);
}

// ---------------- RoPE apply (in-place) ----------------
__global__ void rope_apply_kernel(float* __restrict__ x, int heads,
                                  const float* __restrict__ ctab,
                                  const float* __restrict__ stab) {
    int i = blockIdx.x * blockDim.x + threadIdx.x;
    if (i >= N_TOK * heads * 64) return;
    int fi = i & 63;
    int h  = (i >> 6) % heads;
    int t  = i / (64 * heads);
    int s  = t & (SEQ - 1);
    float c  = ctab[s * 64 + fi];
    float sn = stab[s * 64 + fi];
    float* p = x + (size_t)t * (heads * HD) + h * HD + fi;
    float x1 = p[0], x2 = p[64];
    p[0]  = x1 * c  - x2 * sn;
    p[64] = x1 * sn + x2 * c;
}

// ---------------- RMSNorm -> bf16 hi/lo ----------------
__global__ __launch_bounds__(256) void rmsnorm_bf16_kernel(const float* __restrict__ x,
                                                           const float* __restrict__ w,
                                                           __nv_bfloat16* __restrict__ hi,
                                                           __nv_bfloat16* __restrict__ lo) {
    int row = blockIdx.x;
    int t = threadIdx.x;
    const float4* xr = (const float4*)(x + (size_t)row * DMODEL);
    float4 v0 = xr[t];
    float4 v1 = xr[t + 256];
    float ss = v0.x*v0.x + v0.y*v0.y + v0.z*v0.z + v0.w*v0.w
             + v1.x*v1.x + v1.y*v1.y + v1.z*v1.z + v1.w*v1.w;
    #pragma unroll
    for (int off = 16; off; off >>= 1) ss += __shfl_xor_sync(0xffffffffu, ss, off);
    __shared__ float red[8];
    if ((t & 31) == 0) red[t >> 5] = ss;
    __syncthreads();
    float tot = red[0] + red[1] + red[2] + red[3] + red[4] + red[5] + red[6] + red[7];
    float inv = rsqrtf(tot * (1.0f / DMODEL) + 1e-6f);
    const float4* wr = (const float4*)w;
    #pragma unroll
    for (int half = 0; half < 2; half++) {
        float4 v = half ? v1 : v0;
        float4 wv = wr[t + half * 256];
        float y0 = v.x * inv * wv.x, y1 = v.y * inv * wv.y;
        float y2 = v.z * inv * wv.z, y3 = v.w * inv * wv.w;
        __nv_bfloat16 h0 = __float2bfloat16_rn(y0), h1 = __float2bfloat16_rn(y1);
        __nv_bfloat16 h2 = __float2bfloat16_rn(y2), h3 = __float2bfloat16_rn(y3);
        __nv_bfloat16 l0 = __float2bfloat16_rn(y0 - __bfloat162float(h0));
        __nv_bfloat16 l1 = __float2bfloat16_rn(y1 - __bfloat162float(h1));
        __nv_bfloat16 l2 = __float2bfloat16_rn(y2 - __bfloat162float(h2));
        __nv_bfloat16 l3 = __float2bfloat16_rn(y3 - __bfloat162float(h3));
        size_t o2 = (size_t)row * (DMODEL / 2) + (t + half * 256) * 2;
        ((__nv_bfloat162*)hi)[o2]     = __nv_bfloat162(h0, h1);
        ((__nv_bfloat162*)hi)[o2 + 1] = __nv_bfloat162(h2, h3);
        ((__nv_bfloat162*)lo)[o2]     = __nv_bfloat162(l0, l1);
        ((__nv_bfloat162*)lo)[o2 + 1] = __nv_bfloat162(l2, l3);
    }
}

// ---------------- bf16x3 GEMM on mma.sync ----------------
// C[N_TOK, M] = (Ahi+Alo)[N_TOK, K] * (Whi+Wlo)[M, K]^T (+ res), fp32 out.
// 128x128 CTA tile, BK=64, cp.async 2-stage double buffer, SW128 swizzle,
// 8 warps (2m x 4n), warp tile 64x32, mma.sync m16n8k16 bf16, 3 products.
__global__ __launch_bounds__(256) void gemm_mma(
    const __nv_bfloat16* __restrict__ Ahi, const __nv_bfloat16* __restrict__ Alo,
    const __nv_bfloat16* __restrict__ Whi, const __nv_bfloat16* __restrict__ Wlo,
    float* __restrict__ C, const float* __restrict__ res, int M, int K) {
    extern __shared__ char dsm[];
    char* sbase = (char*)(((uintptr_t)dsm + 1023) & ~(uintptr_t)1023);
    const uint32_t sb = smem_u32(sbase);

    const int tid  = threadIdx.x;
    const int wid  = tid >> 5;
    const int lane = tid & 31;
    const int wm = wid & 1;        // 0..1  (m)
    const int wn = wid >> 1;       // 0..3  (n)
    const int n0 = blockIdx.x * BN;    // token rows
    const int m0 = blockIdx.y * BM;    // output cols (W rows)

    const __nv_bfloat16* srcs[4] = {
        Ahi + (size_t)n0 * K, Alo + (size_t)n0 * K,
        Whi + (size_t)m0 * K, Wlo + (size_t)m0 * K };

    // per-lane fragment address components
    const int a_r   = (lane & 7) + ((lane >> 3) & 1) * 8;
    const int a_kc8 = (lane >> 4) << 3;
    const int b_r   = (lane & 7) + ((lane >> 4) << 3);
    const int b_kc8 = ((lane >> 3) & 1) << 3;

    float acc[4][4][4];
    #pragma unroll
    for (int i = 0; i < 4; i++)
        #pragma unroll
        for (int j = 0; j < 4; j++)
            #pragma unroll
            for (int q = 0; q < 4; q++) acc[i][j][q] = 0.f;

    const int niter = K / BK;

    // prologue: stage 0
    {
        #pragma unroll
        for (int i = 0; i < 16; i++) {
            int cid = tid + i * 256;
            int t   = cid >> 10;
            int idx = cid & 1023;
            int r   = idx >> 3;
            int c   = idx & 7;
            uint32_t off = (uint32_t)(r * 128 + c * 16);
            cp16(sb + t * TILE_BYTES + SWZ(off), srcs[t] + (size_t)r * K + c * 8);
        }
        asm volatile("cp.async.commit_group;" ::: "memory");
    }

    for (int it = 0; it < niter; it++) {
        const int buf = it & 1;
        if (it + 1 < niter) {
            const int kb = (it + 1) * BK;
            const uint32_t stg = sb + (buf ^ 1) * STAGE_BYTES;
            #pragma unroll
            for (int i = 0; i < 16; i++) {
                int cid = tid + i * 256;
                int t   = cid >> 10;
                int idx = cid & 1023;
                int r   = idx >> 3;
                int c   = idx & 7;
                uint32_t off = (uint32_t)(r * 128 + c * 16);
                cp16(stg + t * TILE_BYTES + SWZ(off), srcs[t] + (size_t)r * K + kb + c * 8);
            }
            asm volatile("cp.async.commit_group;" ::: "memory");
            asm volatile("cp.async.wait_group 1;" ::: "memory");
        } else {
            asm volatile("cp.async.wait_group 0;" ::: "memory");
        }
        __syncthreads();

        const uint32_t stg = sb + buf * STAGE_BYTES;
        const uint32_t sAh = stg;
        const uint32_t sAl = stg + TILE_BYTES;
        const uint32_t sWh = stg + 2 * TILE_BYTES;
        const uint32_t sWl = stg + 3 * TILE_BYTES;

        #pragma unroll
        for (int ks = 0; ks < 4; ks++) {
            const int kk = ks * 16;
            uint32_t ah[4][4], al[4][4], bh[4][2], bl[4][2];
            #pragma unroll
            for (int mt = 0; mt < 4; mt++) {
                int r = wm * 64 + mt * 16 + a_r;
                uint32_t off = SWZ((uint32_t)(r * 128 + (kk + a_kc8) * 2));
                ldm_x4(ah[mt], sAh + off);
                ldm_x4(al[mt], sAl + off);
            }
            #pragma unroll
            for (int np = 0; np < 2; np++) {
                int r = wn * 32 + np * 16 + b_r;
                uint32_t off = SWZ((uint32_t)(r * 128 + (kk + b_kc8) * 2));
                uint32_t t4[4];
                ldm_x4(t4, sWh + off);
                bh[np*2][0] = t4[0]; bh[np*2][1] = t4[1];
                bh[np*2+1][0] = t4[2]; bh[np*2+1][1] = t4[3];
                ldm_x4(t4, sWl + off);
                bl[np*2][0] = t4[0]; bl[np*2][1] = t4[1];
                bl[np*2+1][0] = t4[2]; bl[np*2+1][1] = t4[3];
            }
            #pragma unroll
            for (int mt = 0; mt < 4; mt++)
                #pragma unroll
                for (int nt = 0; nt < 4; nt++) {
                    mma_bf16(acc[mt][nt], ah[mt][0], ah[mt][1], ah[mt][2], ah[mt][3],
                             bh[nt][0], bh[nt][1]);
                    mma_bf16(acc[mt][nt], ah[mt][0], ah[mt][1], ah[mt][2], ah[mt][3],
                             bl[nt][0], bl[nt][1]);
                    mma_bf16(acc[mt][nt], al[mt][0], al[mt][1], al[mt][2], al[mt][3],
                             bh[nt][0], bh[nt][1]);
                }
        }
        __syncthreads();
    }

    // epilogue
    const int rb = n0 + wm * 64 + (lane >> 2);
    const int cb = m0 + wn * 32 + (lane & 3) * 2;
    #pragma unroll
    for (int mt = 0; mt < 4; mt++)
        #pragma unroll
        for (int nt = 0; nt < 4; nt++) {
            int r = rb + mt * 16;
            int c = cb + nt * 8;
            float2 v0 = make_float2(acc[mt][nt][0], acc[mt][nt][1]);
            float2 v1 = make_float2(acc[mt][nt][2], acc[mt][nt][3]);
            if (res) {
                float2 r0 = *(const float2*)(res + (size_t)r * M + c);
                float2 r1 = *(const float2*)(res + (size_t)(r + 8) * M + c);
                v0.x += r0.x; v0.y += r0.y;
                v1.x += r1.x; v1.y += r1.y;
            }
            *(float2*)(C + (size_t)r * M + c)       = v0;
            *(float2*)(C + (size_t)(r + 8) * M + c) = v1;
        }
}

// ---------------- causal attention, online softmax, 4 queries per warp --------
#define QPW 4
__global__ __launch_bounds__(256) void attn_kernel(const float* __restrict__ q,
                                                   const float* __restrict__ k,
                                                   const float* __restrict__ v,
                                                   float* __restrict__ out) {
    int gwarp = (blockIdx.x * blockDim.x + threadIdx.x) >> 5;
    int lane = threadIdx.x & 31;
    int qg = gwarp & 255;
    int bh = gwarp >> 8;
    int b = bh >> 4;
    int h = bh & 15;
    int kvh = h >> 1;
    int q0 = qg * QPW;

    const float scale = 0.08838834764831845f;

    float4 qv[QPW];
    float  m[QPW], l[QPW];
    float4 acc[QPW];
    #pragma unroll
    for (int r = 0; r < QPW; r++) {
        qv[r] = *(const float4*)&q[(size_t)(b * SEQ + q0 + r) * DMODEL + h * HD + lane * 4];
        m[r] = -1e30f;
        l[r] = 0.f;
        acc[r] = make_float4(0.f, 0.f, 0.f, 0.f);
    }

    const float* kbase = k + (size_t)b * SEQ * KVD + kvh * HD + lane * 4;
    const float* vbase = v + (size_t)b * SEQ * KVD + kvh * HD + lane * 4;
    int jmax = q0 + QPW - 1;

    for (int j = 0; j <= jmax; j++) {
        float4 kv4 = *(const float4*)(kbase + (size_t)j * KVD);
        float d[QPW];
        #pragma unroll
        for (int r = 0; r < QPW; r++)
            d[r] = qv[r].x * kv4.x + qv[r].y * kv4.y + qv[r].z * kv4.z + qv[r].w * kv4.w;
        #pragma unroll
        for (int off = 16; off; off >>= 1) {
            #pragma unroll
            for (int r = 0; r < QPW; r++)
                d[r] += __shfl_xor_sync(0xffffffffu, d[r], off);
        }
        float4 vv = *(const float4*)(vbase + (size_t)j * KVD);
        #pragma unroll
        for (int r = 0; r < QPW; r++) {
            if (j <= q0 + r) {
                float dr = d[r] * scale;
                float mn = fmaxf(m[r], dr);
                float corr = __expf(m[r] - mn);
                float p = __expf(dr - mn);
                l[r] = l[r] * corr + p;
                acc[r].x = acc[r].x * corr + p * vv.x;
                acc[r].y = acc[r].y * corr + p * vv.y;
                acc[r].z = acc[r].z * corr + p * vv.z;
                acc[r].w = acc[r].w * corr + p * vv.w;
                m[r] = mn;
            }
        }
    }

    #pragma unroll
    for (int r = 0; r < QPW; r++) {
        float inv = 1.f / l[r];
        float4 o = make_float4(acc[r].x * inv, acc[r].y * inv, acc[r].z * inv, acc[r].w * inv);
        *(float4*)&out[(size_t)(b * SEQ + q0 + r) * DMODEL + h * HD + lane * 4] = o;
    }
}

// ---------------- silu(gate)*up -> bf16 hi/lo ----------------
__global__ void silu_mul_bf16_kernel(const float* __restrict__ gate,
                                     const float* __restrict__ up,
                                     __nv_bfloat16* __restrict__ hi,
                                     __nv_bfloat16* __restrict__ lo) {
    int i4 = blockIdx.x * blockDim.x + threadIdx.x;
    if (i4 >= N_TOK * (FFDIM / 4)) return;
    float4 g = ((const float4*)gate)[i4];
    float4 u = ((const float4*)up)[i4];
    float y0 = g.x / (1.f + expf(-g.x)) * u.x;
    float y1 = g.y / (1.f + expf(-g.y)) * u.y;
    float y2 = g.z / (1.f + expf(-g.z)) * u.z;
    float y3 = g.w / (1.f + expf(-g.w)) * u.w;
    __nv_bfloat16 h0 = __float2bfloat16_rn(y0), h1 = __float2bfloat16_rn(y1);
    __nv_bfloat16 h2 = __float2bfloat16_rn(y2), h3 = __float2bfloat16_rn(y3);
    __nv_bfloat16 l0 = __float2bfloat16_rn(y0 - __bfloat162float(h0));
    __nv_bfloat16 l1 = __float2bfloat16_rn(y1 - __bfloat162float(h1));
    __nv_bfloat16 l2 = __float2bfloat16_rn(y2 - __bfloat162float(h2));
    __nv_bfloat16 l3 = __float2bfloat16_rn(y3 - __bfloat162float(h3));
    ((__nv_bfloat162*)hi)[i4 * 2]     = __nv_bfloat162(h0, h1);
    ((__nv_bfloat162*)hi)[i4 * 2 + 1] = __nv_bfloat162(h2, h3);
    ((__nv_bfloat162*)lo)[i4 * 2]     = __nv_bfloat162(l0, l1);
    ((__nv_bfloat162*)lo)[i4 * 2 + 1] = __nv_bfloat162(l2, l3);
}

// ---------------- host-side orchestration ----------------
static void* sym(const void* devsym) {
    void* p = nullptr;
    cudaGetSymbolAddress(&p, devsym);
    return p;
}

extern "C" void kernel_launch(void* const* d_in, const int* in_sizes, int n_in,
                              void* d_out, int out_size) {
    int e = 1;
    if (n_in >= 15) e = 3;
    const int*   ids   = (const int*)d_in[0];
    const float* embed = (const float*)d_in[e + 0];
    const float* ln1   = (const float*)d_in[e + 1];
    const float* wq    = (const float*)d_in[e + 2];
    const float* wk    = (const float*)d_in[e + 3];
    const float* wv    = (const float*)d_in[e + 4];
    const float* wo    = (const float*)d_in[e + 5];
    const float* ln2   = (const float*)d_in[e + 6];
    const float* wg    = (const float*)d_in[e + 7];
    const float* wu    = (const float*)d_in[e + 8];
    const float* wd    = (const float*)d_in[e + 9];
    const float* nw    = (const float*)d_in[e + 10];
    const float* lmh   = (const float*)d_in[e + 11];
    float* out = (float*)d_out;

    float* x    = (float*)sym(g_x);
    float* q    = (float*)sym(g_q);
    float* kbuf = (float*)sym(g_k);
    float* vbuf = (float*)sym(g_v);
    float* attn = (float*)sym(g_attn);
    float* gate = (float*)sym(g_gate);
    float* up   = (float*)sym(g_up);
    float* ctab = (float*)sym(g_cos);
    float* stab = (float*)sym(g_sin);

    __nv_bfloat16* xnh = (__nv_bfloat16*)sym(g_xn_h);
    __nv_bfloat16* xnl = (__nv_bfloat16*)sym(g_xn_l);
    __nv_bfloat16* ath = (__nv_bfloat16*)sym(g_at_h);
    __nv_bfloat16* atl = (__nv_bfloat16*)sym(g_at_l);
    __nv_bfloat16* glh = (__nv_bfloat16*)sym(g_gl_h);
    __nv_bfloat16* gll = (__nv_bfloat16*)sym(g_gl_l);

    __nv_bfloat16* wqh = (__nv_bfloat16*)sym(g_wq_h); __nv_bfloat16* wql = (__nv_bfloat16*)sym(g_wq_l);
    __nv_bfloat16* wkh = (__nv_bfloat16*)sym(g_wk_h); __nv_bfloat16* wkl = (__nv_bfloat16*)sym(g_wk_l);
    __nv_bfloat16* wvh = (__nv_bfloat16*)sym(g_wv_h); __nv_bfloat16* wvl = (__nv_bfloat16*)sym(g_wv_l);
    __nv_bfloat16* woh = (__nv_bfloat16*)sym(g_wo_h); __nv_bfloat16* wol = (__nv_bfloat16*)sym(g_wo_l);
    __nv_bfloat16* wgh = (__nv_bfloat16*)sym(g_wg_h); __nv_bfloat16* wgl = (__nv_bfloat16*)sym(g_wg_l);
    __nv_bfloat16* wuh = (__nv_bfloat16*)sym(g_wu_h); __nv_bfloat16* wul = (__nv_bfloat16*)sym(g_wu_l);
    __nv_bfloat16* wdh = (__nv_bfloat16*)sym(g_wd_h); __nv_bfloat16* wdl = (__nv_bfloat16*)sym(g_wd_l);
    __nv_bfloat16* lmhh = (__nv_bfloat16*)sym(g_lm_h); __nv_bfloat16* lmhl = (__nv_bfloat16*)sym(g_lm_l);

    cudaFuncSetAttribute(gemm_mma, cudaFuncAttributeMaxDynamicSharedMemorySize, GEMM_SMEM);

    dim3 blk(256);

    // weight conversions (once per launch)
    {
        int n;
        n = NLAYER * DMODEL * DMODEL / 4; cvt_kernel<<<(n + 255) / 256, blk>>>(wq, wqh, wql, n);
        n = NLAYER * KVD * DMODEL / 4;    cvt_kernel<<<(n + 255) / 256, blk>>>(wk, wkh, wkl, n);
        n = NLAYER * KVD * DMODEL / 4;    cvt_kernel<<<(n + 255) / 256, blk>>>(wv, wvh, wvl, n);
        n = NLAYER * DMODEL * DMODEL / 4; cvt_kernel<<<(n + 255) / 256, blk>>>(wo, woh, wol, n);
        n = NLAYER * FFDIM * DMODEL / 4;  cvt_kernel<<<(n + 255) / 256, blk>>>(wg, wgh, wgl, n);
        n = NLAYER * FFDIM * DMODEL / 4;  cvt_kernel<<<(n + 255) / 256, blk>>>(wu, wuh, wul, n);
        n = NLAYER * DMODEL * FFDIM / 4;  cvt_kernel<<<(n + 255) / 256, blk>>>(wd, wdh, wdl, n);
        n = VOCAB * DMODEL / 4;           cvt_kernel<<<(n + 255) / 256, blk>>>(lmh, lmhh, lmhl, n);
    }

    embed_kernel<<<(N_TOK * DMODEL / 4 + 255) / 256, blk>>>(ids, embed, x);
    rope_table_kernel<<<(SEQ * 64 + 255) / 256, blk>>>(ctab, stab);

    for (int L = 0; L < NLAYER; L++) {
        const __nv_bfloat16* qwh = wqh + (size_t)L * DMODEL * DMODEL;
        const __nv_bfloat16* qwl = wql + (size_t)L * DMODEL * DMODEL;
        const __nv_bfloat16* kwh = wkh + (size_t)L * KVD * DMODEL;
        const __nv_bfloat16* kwl = wkl + (size_t)L * KVD * DMODEL;
        const __nv_bfloat16* vwh = wvh + (size_t)L * KVD * DMODEL;
        const __nv_bfloat16* vwl = wvl + (size_t)L * KVD * DMODEL;
        const __nv_bfloat16* owh = woh + (size_t)L * DMODEL * DMODEL;
        const __nv_bfloat16* owl = wol + (size_t)L * DMODEL * DMODEL;
        const __nv_bfloat16* gwh = wgh + (size_t)L * FFDIM * DMODEL;
        const __nv_bfloat16* gwl = wgl + (size_t)L * FFDIM * DMODEL;
        const __nv_bfloat16* uwh = wuh + (size_t)L * FFDIM * DMODEL;
        const __nv_bfloat16* uwl = wul + (size_t)L * FFDIM * DMODEL;
        const __nv_bfloat16* dwh = wdh + (size_t)L * DMODEL * FFDIM;
        const __nv_bfloat16* dwl = wdl + (size_t)L * DMODEL * FFDIM;
        const float* l1w = ln1 + (size_t)L * DMODEL;
        const float* l2w = ln2 + (size_t)L * DMODEL;

        // attn block
        rmsnorm_bf16_kernel<<<N_TOK, blk>>>(x, l1w, xnh, xnl);
        gemm_mma<<<dim3(N_TOK / BN, DMODEL / BM), blk, GEMM_SMEM>>>(xnh, xnl, qwh, qwl, q,    nullptr, DMODEL, DMODEL);
        gemm_mma<<<dim3(N_TOK / BN, KVD    / BM), blk, GEMM_SMEM>>>(xnh, xnl, kwh, kwl, kbuf, nullptr, KVD,    DMODEL);
        gemm_mma<<<dim3(N_TOK / BN, KVD    / BM), blk, GEMM_SMEM>>>(xnh, xnl, vwh, vwl, vbuf, nullptr, KVD,    DMODEL);
        rope_apply_kernel<<<(N_TOK * NH  * 64 + 255) / 256, blk>>>(q,    NH,  ctab, stab);
        rope_apply_kernel<<<(N_TOK * NKV * 64 + 255) / 256, blk>>>(kbuf, NKV, ctab, stab);
        attn_kernel<<<(BATCH * NH * (SEQ / QPW)) * 32 / 256, blk>>>(q, kbuf, vbuf, attn);
        { int n = N_TOK * DMODEL / 4; cvt_kernel<<<(n + 255) / 256, blk>>>(attn, ath, atl, n); }
        gemm_mma<<<dim3(N_TOK / BN, DMODEL / BM), blk, GEMM_SMEM>>>(ath, atl, owh, owl, x, x, DMODEL, DMODEL);

        // ffn block
        rmsnorm_bf16_kernel<<<N_TOK, blk>>>(x, l2w, xnh, xnl);
        gemm_mma<<<dim3(N_TOK / BN, FFDIM / BM), blk, GEMM_SMEM>>>(xnh, xnl, gwh, gwl, gate, nullptr, FFDIM, DMODEL);
        gemm_mma<<<dim3(N_TOK / BN, FFDIM / BM), blk, GEMM_SMEM>>>(xnh, xnl, uwh, uwl, up,   nullptr, FFDIM, DMODEL);
        silu_mul_bf16_kernel<<<(N_TOK * FFDIM / 4 + 255) / 256, blk>>>(gate, up, glh, gll);
        gemm_mma<<<dim3(N_TOK / BN, DMODEL / BM), blk, GEMM_SMEM>>>(glh, gll, dwh, dwl, x, x, DMODEL, FFDIM);
    }

    // final norm + lm_head
    rmsnorm_bf16_kernel<<<N_TOK, blk>>>(x, nw, xnh, xnl);
    gemm_mma<<<dim3(N_TOK / BN, VOCAB / BM), blk, GEMM_SMEM>>>(xnh, xnl, lmhh, lmhl, out, nullptr, VOCAB, DMODEL);
}

// round 17
// speedup vs baseline: 2.6472x; 1.0457x over previous
#include <cuda_runtime.h>
#include <cuda_bf16.h>
#include <math.h>
#include <stdint.h>

// Problem constants
#define N_TOK  2048   // B*S
#define SEQ    1024
#define BATCH  2
#define DMODEL 2048
#define KVD    1024
#define FFDIM  8192
#define NLAYER 4
#define NH     16
#define NKV    8
#define HD     128
#define VOCAB  32000
#define QKVD   (DMODEL + 2 * KVD)   // 4096 fused qkv cols
#define GUD    (2 * FFDIM)          // 16384 fused gate+up cols

// GEMM tiling (mma.sync path; tcgen05 unavailable: harness PTX targets compute_103)
#define BN 128
#define BM 256
#define BK 64
#define A_TILE_BYTES 16384          // 128 rows x 64 bf16
#define W_TILE_BYTES 32768          // 256 rows x 64 bf16
#define STAGE_BYTES (2 * A_TILE_BYTES + 2 * W_TILE_BYTES)   // 96 KB
#define GEMM_SMEM (2 * STAGE_BYTES + 1024)

#define SWZ(off) ((off) ^ (((off) >> 3) & 0x70))

// ---------------- scratch (device globals; no allocation allowed) ----------
__device__ float g_x   [N_TOK * DMODEL];
__device__ float g_qkv [N_TOK * QKVD];
__device__ float g_gu  [N_TOK * GUD];
__device__ float g_cos [SEQ * 64];
__device__ float g_sin [SEQ * 64];

// bf16 hi/lo activations
__device__ __align__(128) __nv_bfloat16 g_xn_h [N_TOK * DMODEL];
__device__ __align__(128) __nv_bfloat16 g_xn_l [N_TOK * DMODEL];
__device__ __align__(128) __nv_bfloat16 g_at_h [N_TOK * DMODEL];
__device__ __align__(128) __nv_bfloat16 g_at_l [N_TOK * DMODEL];
__device__ __align__(128) __nv_bfloat16 g_gl_h [N_TOK * FFDIM];
__device__ __align__(128) __nv_bfloat16 g_gl_l [N_TOK * FFDIM];

// bf16 hi/lo weights (qkv and gate/up fused row-wise per layer)
__device__ __align__(128) __nv_bfloat16 g_wqkv_h[NLAYER * QKVD * DMODEL];
__device__ __align__(128) __nv_bfloat16 g_wqkv_l[NLAYER * QKVD * DMODEL];
__device__ __align__(128) __nv_bfloat16 g_wo_h  [NLAYER * DMODEL * DMODEL];
__device__ __align__(128) __nv_bfloat16 g_wo_l  [NLAYER * DMODEL * DMODEL];
__device__ __align__(128) __nv_bfloat16 g_wgu_h [NLAYER * GUD * DMODEL];
__device__ __align__(128) __nv_bfloat16 g_wgu_l [NLAYER * GUD * DMODEL];
__device__ __align__(128) __nv_bfloat16 g_wd_h  [NLAYER * DMODEL * FFDIM];
__device__ __align__(128) __nv_bfloat16 g_wd_l  [NLAYER * DMODEL * FFDIM];
__device__ __align__(128) __nv_bfloat16 g_lm_h  [VOCAB * DMODEL];
__device__ __align__(128) __nv_bfloat16 g_lm_l  [VOCAB * DMODEL];

// ---------------- PTX helpers (base ISA only) ----------------
__device__ __forceinline__ uint32_t smem_u32(const void* p) {
    uint32_t a;
    asm("{ .reg .u64 t; cvta.to.shared.u64 t, %1; cvt.u32.u64 %0, t; }" : "=r"(a) : "l"(p));
    return a;
}

__device__ __forceinline__ void cp16(uint32_t s, const void* g) {
    asm volatile("cp.async.cg.shared.global [%0], [%1], 16;" :: "r"(s), "l"(g));
}

__device__ __forceinline__ void ldm_x4(uint32_t* d, uint32_t addr) {
    asm volatile("ldmatrix.sync.aligned.m8n8.x4.shared.b16 {%0,%1,%2,%3}, [%4];"
        : "=r"(d[0]), "=r"(d[1]), "=r"(d[2]), "=r"(d[3]) : "r"(addr));
}

__device__ __forceinline__ void mma_bf16(float* c, const uint32_t* a,
                                         uint32_t b0, uint32_t b1) {
    asm volatile("mma.sync.aligned.m16n8k16.row.col.f32.bf16.bf16.f32 "
        "{%0,%1,%2,%3}, {%4,%5,%6,%7}, {%8,%9}, {%0,%1,%2,%3};"
        : "+f"(c[0]), "+f"(c[1]), "+f"(c[2]), "+f"(c[3])
        : "r"(a[0]), "r"(a[1]), "r"(a[2]), "r"(a[3]), "r"(b0), "r"(b1));
}

// ---------------- embedding gather ----------------
__global__ void embed_kernel(const int* __restrict__ ids,
                             const float* __restrict__ embed,
                             float* __restrict__ out) {
    int i4 = blockIdx.x * blockDim.x + threadIdx.x;
    if (i4 >= N_TOK * (DMODEL / 4)) return;
    int tok  = i4 >> 9;
    int col4 = i4 & 511;
    int id = ids[tok];
    ((float4*)out)[i4] = ((const float4*)(embed + (size_t)id * DMODEL))[col4];
}

// ---------------- fp32 -> bf16 hi/lo conversion, strided into fused layout ----
// src: [L][rpl][cols]; dst row = layer*fused_rows + row_off + r, width cols.
__global__ void cvt_fused_kernel(const float* __restrict__ src,
                                 __nv_bfloat16* __restrict__ hi,
                                 __nv_bfloat16* __restrict__ lo,
                                 int rpl, int row_off, int fused_rows,
                                 int cols4, int n4) {
    int i4 = blockIdx.x * blockDim.x + threadIdx.x;
    if (i4 >= n4) return;
    int rg = i4 / cols4;
    int c4 = i4 - rg * cols4;
    int layer = rg / rpl;
    int r = rg - layer * rpl;
    size_t drow = (size_t)layer * fused_rows + row_off + r;
    size_t d2 = (drow * cols4 + c4) * 2;
    float4 v = ((const float4*)src)[i4];
    __nv_bfloat16 h0 = __float2bfloat16_rn(v.x), h1 = __float2bfloat16_rn(v.y);
    __nv_bfloat16 h2 = __float2bfloat16_rn(v.z), h3 = __float2bfloat16_rn(v.w);
    __nv_bfloat16 l0 = __float2bfloat16_rn(v.x - __bfloat162float(h0));
    __nv_bfloat16 l1 = __float2bfloat16_rn(v.y - __bfloat162float(h1));
    __nv_bfloat16 l2 = __float2bfloat16_rn(v.z - __bfloat162float(h2));
    __nv_bfloat16 l3 = __float2bfloat16_rn(v.w - __bfloat162float(h3));
    ((__nv_bfloat162*)hi)[d2]     = __nv_bfloat162(h0, h1);
    ((__nv_bfloat162*)hi)[d2 + 1] = __nv_bfloat162(h2, h3);
    ((__nv_bfloat162*)lo)[d2]     = __nv_bfloat162(l0, l1);
    ((__nv_bfloat162*)lo)[d2 + 1] = __nv_bfloat162(l2, l3);
}

// ---------------- RoPE tables ----------------
__global__ void rope_table_kernel(float* __restrict__ ctab, float* __restrict__ stab) {
    int i = blockIdx.x * blockDim.x + threadIdx.x;
    if (i >= SEQ * 64) return;
    int s  = i >> 6;
    int fi = i & 63;
    double freq = exp(-(double)fi * (log(10000.0) / 64.0));
    double a = (double)s * freq;
    ctab[i] = (float)cos(a);
    stab[i] = (float)sin(a);
}

// ---------------- RoPE apply (in-place, strided) ----------------
__global__ void rope_apply_kernel(float* __restrict__ x, int heads, int rstride,
                                  const float* __restrict__ ctab,
                                  const float* __restrict__ stab) {
    int i = blockIdx.x * blockDim.x + threadIdx.x;
    if (i >= N_TOK * heads * 64) return;
    int fi = i & 63;
    int h  = (i >> 6) % heads;
    int t  = i / (64 * heads);
    int s  = t & (SEQ - 1);
    float c  = ctab[s * 64 + fi];
    float sn = stab[s * 64 + fi];
    float* p = x + (size_t)t * rstride + h * HD + fi;
    float x1 = p[0], x2 = p[64];
    p[0]  = x1 * c  - x2 * sn;
    p[64] = x1 * sn + x2 * c;
}

// ---------------- RMSNorm -> bf16 hi/lo ----------------
__global__ __launch_bounds__(256) void rmsnorm_bf16_kernel(const float* __restrict__ x,
                                                           const float* __restrict__ w,
                                                           __nv_bfloat16* __restrict__ hi,
                                                           __nv_bfloat16* __restrict__ lo) {
    int row = blockIdx.x;
    int t = threadIdx.x;
    const float4* xr = (const float4*)(x + (size_t)row * DMODEL);
    float4 v0 = xr[t];
    float4 v1 = xr[t + 256];
    float ss = v0.x*v0.x + v0.y*v0.y + v0.z*v0.z + v0.w*v0.w
             + v1.x*v1.x + v1.y*v1.y + v1.z*v1.z + v1.w*v1.w;
    #pragma unroll
    for (int off = 16; off; off >>= 1) ss += __shfl_xor_sync(0xffffffffu, ss, off);
    __shared__ float red[8];
    if ((t & 31) == 0) red[t >> 5] = ss;
    __syncthreads();
    float tot = red[0] + red[1] + red[2] + red[3] + red[4] + red[5] + red[6] + red[7];
    float inv = rsqrtf(tot * (1.0f / DMODEL) + 1e-6f);
    const float4* wr = (const float4*)w;
    #pragma unroll
    for (int half = 0; half < 2; half++) {
        float4 v = half ? v1 : v0;
        float4 wv = wr[t + half * 256];
        float y0 = v.x * inv * wv.x, y1 = v.y * inv * wv.y;
        float y2 = v.z * inv * wv.z, y3 = v.w * inv * wv.w;
        __nv_bfloat16 h0 = __float2bfloat16_rn(y0), h1 = __float2bfloat16_rn(y1);
        __nv_bfloat16 h2 = __float2bfloat16_rn(y2), h3 = __float2bfloat16_rn(y3);
        __nv_bfloat16 l0 = __float2bfloat16_rn(y0 - __bfloat162float(h0));
        __nv_bfloat16 l1 = __float2bfloat16_rn(y1 - __bfloat162float(h1));
        __nv_bfloat16 l2 = __float2bfloat16_rn(y2 - __bfloat162float(h2));
        __nv_bfloat16 l3 = __float2bfloat16_rn(y3 - __bfloat162float(h3));
        size_t o2 = (size_t)row * (DMODEL / 2) + (t + half * 256) * 2;
        ((__nv_bfloat162*)hi)[o2]     = __nv_bfloat162(h0, h1);
        ((__nv_bfloat162*)hi)[o2 + 1] = __nv_bfloat162(h2, h3);
        ((__nv_bfloat162*)lo)[o2]     = __nv_bfloat162(l0, l1);
        ((__nv_bfloat162*)lo)[o2 + 1] = __nv_bfloat162(l2, l3);
    }
}

// ---------------- bf16x3 GEMM on mma.sync ----------------
// C[N_TOK, M] = (Ahi+Alo)[N_TOK, K] * (Whi+Wlo)[M, K]^T (+ res), fp32 out.
// 128x256 CTA tile, BK=64, cp.async 2-stage double buffer, SW128 swizzle,
// 8 warps (2m x 4n), warp tile 64x64, mma.sync m16n8k16 bf16, 3 products.
__global__ __launch_bounds__(256) void gemm_mma(
    const __nv_bfloat16* __restrict__ Ahi, const __nv_bfloat16* __restrict__ Alo,
    const __nv_bfloat16* __restrict__ Whi, const __nv_bfloat16* __restrict__ Wlo,
    float* __restrict__ C, const float* __restrict__ res, int M, int K) {
    extern __shared__ char dsm[];
    char* sbase = (char*)(((uintptr_t)dsm + 1023) & ~(uintptr_t)1023);
    const uint32_t sb = smem_u32(sbase);

    const int tid  = threadIdx.x;
    const int wid  = tid >> 5;
    const int lane = tid & 31;
    const int wm = wid & 1;        // 0..1  (m)
    const int wn = wid >> 1;       // 0..3  (n)
    const int n0 = blockIdx.x * BN;    // token rows
    const int m0 = blockIdx.y * BM;    // output cols (W rows)

    const __nv_bfloat16* aA[2] = { Ahi + (size_t)n0 * K, Alo + (size_t)n0 * K };
    const __nv_bfloat16* aW[2] = { Whi + (size_t)m0 * K, Wlo + (size_t)m0 * K };

    // per-lane fragment address components
    const int a_r   = (lane & 7) + ((lane >> 3) & 1) * 8;
    const int a_kc8 = (lane >> 4) << 3;
    const int b_r   = (lane & 7) + ((lane >> 4) << 3);
    const int b_kc8 = ((lane >> 3) & 1) << 3;

    float acc[4][8][4];
    #pragma unroll
    for (int i = 0; i < 4; i++)
        #pragma unroll
        for (int j = 0; j < 8; j++)
            #pragma unroll
            for (int q = 0; q < 4; q++) acc[i][j][q] = 0.f;

    const int niter = K / BK;

    // load one full stage (A hi/lo: 2048 chunks, W hi/lo: 4096 chunks)
    auto load_stage = [&](uint32_t stg, int kb) {
        #pragma unroll
        for (int i = 0; i < 8; i++) {
            int cid = tid + i * 256;
            int t   = cid >> 10;
            int idx = cid & 1023;
            int r   = idx >> 3;
            int c   = idx & 7;
            uint32_t off = (uint32_t)(r * 128 + c * 16);
            cp16(stg + t * A_TILE_BYTES + SWZ(off), aA[t] + (size_t)r * K + kb + c * 8);
        }
        #pragma unroll
        for (int i = 0; i < 16; i++) {
            int cid = tid + i * 256;
            int t   = cid >> 11;
            int idx = cid & 2047;
            int r   = idx >> 3;
            int c   = idx & 7;
            uint32_t off = (uint32_t)(r * 128 + c * 16);
            cp16(stg + 2 * A_TILE_BYTES + t * W_TILE_BYTES + SWZ(off),
                 aW[t] + (size_t)r * K + kb + c * 8);
        }
    };

    load_stage(sb, 0);
    asm volatile("cp.async.commit_group;" ::: "memory");

    for (int it = 0; it < niter; it++) {
        const int buf = it & 1;
        if (it + 1 < niter) {
            load_stage(sb + (buf ^ 1) * STAGE_BYTES, (it + 1) * BK);
            asm volatile("cp.async.commit_group;" ::: "memory");
            asm volatile("cp.async.wait_group 1;" ::: "memory");
        } else {
            asm volatile("cp.async.wait_group 0;" ::: "memory");
        }
        __syncthreads();

        const uint32_t stg = sb + buf * STAGE_BYTES;
        const uint32_t sAh = stg;
        const uint32_t sAl = stg + A_TILE_BYTES;
        const uint32_t sWh = stg + 2 * A_TILE_BYTES;
        const uint32_t sWl = stg + 2 * A_TILE_BYTES + W_TILE_BYTES;

        #pragma unroll
        for (int ks = 0; ks < 4; ks++) {
            const int kk = ks * 16;
            uint32_t ah[4][4], al[4][4], bh[8][2], bl[8][2];
            #pragma unroll
            for (int mt = 0; mt < 4; mt++) {
                int r = wm * 64 + mt * 16 + a_r;
                uint32_t off = SWZ((uint32_t)(r * 128 + (kk + a_kc8) * 2));
                ldm_x4(ah[mt], sAh + off);
                ldm_x4(al[mt], sAl + off);
            }
            #pragma unroll
            for (int np = 0; np < 4; np++) {
                int r = wn * 64 + np * 16 + b_r;
                uint32_t off = SWZ((uint32_t)(r * 128 + (kk + b_kc8) * 2));
                uint32_t t4[4];
                ldm_x4(t4, sWh + off);
                bh[np*2][0] = t4[0]; bh[np*2][1] = t4[1];
                bh[np*2+1][0] = t4[2]; bh[np*2+1][1] = t4[3];
                ldm_x4(t4, sWl + off);
                bl[np*2][0] = t4[0]; bl[np*2][1] = t4[1];
                bl[np*2+1][0] = t4[2]; bl[np*2+1][1] = t4[3];
            }
            #pragma unroll
            for (int mt = 0; mt < 4; mt++)
                #pragma unroll
                for (int nt = 0; nt < 8; nt++) {
                    mma_bf16(acc[mt][nt], ah[mt], bh[nt][0], bh[nt][1]);
                    mma_bf16(acc[mt][nt], ah[mt], bl[nt][0], bl[nt][1]);
                    mma_bf16(acc[mt][nt], al[mt], bh[nt][0], bh[nt][1]);
                }
        }
        __syncthreads();
    }

    // epilogue
    const int rb = n0 + wm * 64 + (lane >> 2);
    const int cb = m0 + wn * 64 + (lane & 3) * 2;
    #pragma unroll
    for (int mt = 0; mt < 4; mt++)
        #pragma unroll
        for (int nt = 0; nt < 8; nt++) {
            int r = rb + mt * 16;
            int c = cb + nt * 8;
            float2 v0 = make_float2(acc[mt][nt][0], acc[mt][nt][1]);
            float2 v1 = make_float2(acc[mt][nt][2], acc[mt][nt][3]);
            if (res) {
                float2 r0 = *(const float2*)(res + (size_t)r * M + c);
                float2 r1 = *(const float2*)(res + (size_t)(r + 8) * M + c);
                v0.x += r0.x; v0.y += r0.y;
                v1.x += r1.x; v1.y += r1.y;
            }
            *(float2*)(C + (size_t)r * M + c)       = v0;
            *(float2*)(C + (size_t)(r + 8) * M + c) = v1;
        }
}

// ---------------- causal attention over fused qkv, writes bf16 hi/lo ----------
#define QPW 4
__global__ __launch_bounds__(256) void attn_kernel(const float* __restrict__ qkv,
                                                   __nv_bfloat16* __restrict__ outh,
                                                   __nv_bfloat16* __restrict__ outl) {
    int gwarp = (blockIdx.x * blockDim.x + threadIdx.x) >> 5;
    int lane = threadIdx.x & 31;
    int qg = gwarp & 255;
    int bh = gwarp >> 8;
    int b = bh >> 4;
    int h = bh & 15;
    int kvh = h >> 1;
    int q0 = qg * QPW;

    const float scale = 0.08838834764831845f;

    float4 qv[QPW];
    float  m[QPW], l[QPW];
    float4 acc[QPW];
    #pragma unroll
    for (int r = 0; r < QPW; r++) {
        qv[r] = *(const float4*)&qkv[(size_t)(b * SEQ + q0 + r) * QKVD + h * HD + lane * 4];
        m[r] = -1e30f;
        l[r] = 0.f;
        acc[r] = make_float4(0.f, 0.f, 0.f, 0.f);
    }

    const float* kbase = qkv + (size_t)b * SEQ * QKVD + DMODEL + kvh * HD + lane * 4;
    const float* vbase = qkv + (size_t)b * SEQ * QKVD + DMODEL + KVD + kvh * HD + lane * 4;
    int jmax = q0 + QPW - 1;

    for (int j = 0; j <= jmax; j++) {
        float4 kv4 = *(const float4*)(kbase + (size_t)j * QKVD);
        float d[QPW];
        #pragma unroll
        for (int r = 0; r < QPW; r++)
            d[r] = qv[r].x * kv4.x + qv[r].y * kv4.y + qv[r].z * kv4.z + qv[r].w * kv4.w;
        #pragma unroll
        for (int off = 16; off; off >>= 1) {
            #pragma unroll
            for (int r = 0; r < QPW; r++)
                d[r] += __shfl_xor_sync(0xffffffffu, d[r], off);
        }
        float4 vv = *(const float4*)(vbase + (size_t)j * QKVD);
        #pragma unroll
        for (int r = 0; r < QPW; r++) {
            if (j <= q0 + r) {
                float dr = d[r] * scale;
                float mn = fmaxf(m[r], dr);
                float corr = __expf(m[r] - mn);
                float p = __expf(dr - mn);
                l[r] = l[r] * corr + p;
                acc[r].x = acc[r].x * corr + p * vv.x;
                acc[r].y = acc[r].y * corr + p * vv.y;
                acc[r].z = acc[r].z * corr + p * vv.z;
                acc[r].w = acc[r].w * corr + p * vv.w;
                m[r] = mn;
            }
        }
    }

    #pragma unroll
    for (int r = 0; r < QPW; r++) {
        float inv = 1.f / l[r];
        float y0 = acc[r].x * inv, y1 = acc[r].y * inv;
        float y2 = acc[r].z * inv, y3 = acc[r].w * inv;
        __nv_bfloat16 h0 = __float2bfloat16_rn(y0), h1 = __float2bfloat16_rn(y1);
        __nv_bfloat16 h2 = __float2bfloat16_rn(y2), h3 = __float2bfloat16_rn(y3);
        __nv_bfloat16 l0 = __float2bfloat16_rn(y0 - __bfloat162float(h0));
        __nv_bfloat16 l1 = __float2bfloat16_rn(y1 - __bfloat162float(h1));
        __nv_bfloat16 l2 = __float2bfloat16_rn(y2 - __bfloat162float(h2));
        __nv_bfloat16 l3 = __float2bfloat16_rn(y3 - __bfloat162float(h3));
        size_t o2 = ((size_t)(b * SEQ + q0 + r) * DMODEL + h * HD + lane * 4) / 2;
        ((__nv_bfloat162*)outh)[o2]     = __nv_bfloat162(h0, h1);
        ((__nv_bfloat162*)outh)[o2 + 1] = __nv_bfloat162(h2, h3);
        ((__nv_bfloat162*)outl)[o2]     = __nv_bfloat162(l0, l1);
        ((__nv_bfloat162*)outl)[o2 + 1] = __nv_bfloat162(l2, l3);
    }
}

// ---------------- silu(gate)*up (fused gu buffer) -> bf16 hi/lo ----------------
__global__ void silu_mul_bf16_kernel(const float* __restrict__ gu,
                                     __nv_bfloat16* __restrict__ hi,
                                     __nv_bfloat16* __restrict__ lo) {
    int i4 = blockIdx.x * blockDim.x + threadIdx.x;
    if (i4 >= N_TOK * (FFDIM / 4)) return;
    int t  = i4 >> 11;           // / (FFDIM/4)
    int c4 = i4 & 2047;
    const float* row = gu + (size_t)t * GUD;
    float4 g = ((const float4*)row)[c4];
    float4 u = ((const float4*)(row + FFDIM))[c4];
    float y0 = g.x / (1.f + expf(-g.x)) * u.x;
    float y1 = g.y / (1.f + expf(-g.y)) * u.y;
    float y2 = g.z / (1.f + expf(-g.z)) * u.z;
    float y3 = g.w / (1.f + expf(-g.w)) * u.w;
    __nv_bfloat16 h0 = __float2bfloat16_rn(y0), h1 = __float2bfloat16_rn(y1);
    __nv_bfloat16 h2 = __float2bfloat16_rn(y2), h3 = __float2bfloat16_rn(y3);
    __nv_bfloat16 l0 = __float2bfloat16_rn(y0 - __bfloat162float(h0));
    __nv_bfloat16 l1 = __float2bfloat16_rn(y1 - __bfloat162float(h1));
    __nv_bfloat16 l2 = __float2bfloat16_rn(y2 - __bfloat162float(h2));
    __nv_bfloat16 l3 = __float2bfloat16_rn(y3 - __bfloat162float(h3));
    ((__nv_bfloat162*)hi)[i4 * 2]     = __nv_bfloat162(h0, h1);
    ((__nv_bfloat162*)hi)[i4 * 2 + 1] = __nv_bfloat162(h2, h3);
    ((__nv_bfloat162*)lo)[i4 * 2]     = __nv_bfloat162(l0, l1);
    ((__nv_bfloat162*)lo)[i4 * 2 + 1] = __nv_bfloat162(l2, l3);
}

// ---------------- host-side orchestration ----------------
static void* sym(const void* devsym) {
    void* p = nullptr;
    cudaGetSymbolAddress(&p, devsym);
    return p;
}

extern "C" void kernel_launch(void* const* d_in, const int* in_sizes, int n_in,
                              void* d_out, int out_size) {
    int e = 1;
    if (n_in >= 15) e = 3;
    const int*   ids   = (const int*)d_in[0];
    const float* embed = (const float*)d_in[e + 0];
    const float* ln1   = (const float*)d_in[e + 1];
    const float* wq    = (const float*)d_in[e + 2];
    const float* wk    = (const float*)d_in[e + 3];
    const float* wv    = (const float*)d_in[e + 4];
    const float* wo    = (const float*)d_in[e + 5];
    const float* ln2   = (const float*)d_in[e + 6];
    const float* wg    = (const float*)d_in[e + 7];
    const float* wu    = (const float*)d_in[e + 8];
    const float* wd    = (const float*)d_in[e + 9];
    const float* nw    = (const float*)d_in[e + 10];
    const float* lmh   = (const float*)d_in[e + 11];
    float* out = (float*)d_out;

    float* x    = (float*)sym(g_x);
    float* qkv  = (float*)sym(g_qkv);
    float* gu   = (float*)sym(g_gu);
    float* ctab = (float*)sym(g_cos);
    float* stab = (float*)sym(g_sin);

    __nv_bfloat16* xnh = (__nv_bfloat16*)sym(g_xn_h);
    __nv_bfloat16* xnl = (__nv_bfloat16*)sym(g_xn_l);
    __nv_bfloat16* ath = (__nv_bfloat16*)sym(g_at_h);
    __nv_bfloat16* atl = (__nv_bfloat16*)sym(g_at_l);
    __nv_bfloat16* glh = (__nv_bfloat16*)sym(g_gl_h);
    __nv_bfloat16* gll = (__nv_bfloat16*)sym(g_gl_l);

    __nv_bfloat16* wqkvh = (__nv_bfloat16*)sym(g_wqkv_h);
    __nv_bfloat16* wqkvl = (__nv_bfloat16*)sym(g_wqkv_l);
    __nv_bfloat16* woh   = (__nv_bfloat16*)sym(g_wo_h);
    __nv_bfloat16* wol   = (__nv_bfloat16*)sym(g_wo_l);
    __nv_bfloat16* wguh  = (__nv_bfloat16*)sym(g_wgu_h);
    __nv_bfloat16* wgul  = (__nv_bfloat16*)sym(g_wgu_l);
    __nv_bfloat16* wdh   = (__nv_bfloat16*)sym(g_wd_h);
    __nv_bfloat16* wdl   = (__nv_bfloat16*)sym(g_wd_l);
    __nv_bfloat16* lmhh  = (__nv_bfloat16*)sym(g_lm_h);
    __nv_bfloat16* lmhl  = (__nv_bfloat16*)sym(g_lm_l);

    cudaFuncSetAttribute(gemm_mma, cudaFuncAttributeMaxDynamicSharedMemorySize, GEMM_SMEM);

    dim3 blk(256);

    // weight conversions into fused hi/lo layouts (once per launch)
    {
        int n;
        // qkv fused: wq rows 0..2047, wk 2048..3071, wv 3072..4095 per layer
        n = NLAYER * DMODEL * DMODEL / 4;
        cvt_fused_kernel<<<(n + 255) / 256, blk>>>(wq, wqkvh, wqkvl, DMODEL, 0,            QKVD, 512, n);
        n = NLAYER * KVD * DMODEL / 4;
        cvt_fused_kernel<<<(n + 255) / 256, blk>>>(wk, wqkvh, wqkvl, KVD,    DMODEL,       QKVD, 512, n);
        cvt_fused_kernel<<<(n + 255) / 256, blk>>>(wv, wqkvh, wqkvl, KVD,    DMODEL + KVD, QKVD, 512, n);
        // wo
        n = NLAYER * DMODEL * DMODEL / 4;
        cvt_fused_kernel<<<(n + 255) / 256, blk>>>(wo, woh, wol, DMODEL, 0, DMODEL, 512, n);
        // gate/up fused
        n = NLAYER * FFDIM * DMODEL / 4;
        cvt_fused_kernel<<<(n + 255) / 256, blk>>>(wg, wguh, wgul, FFDIM, 0,     GUD, 512, n);
        cvt_fused_kernel<<<(n + 255) / 256, blk>>>(wu, wguh, wgul, FFDIM, FFDIM, GUD, 512, n);
        // down (K = FFDIM)
        n = NLAYER * DMODEL * FFDIM / 4;
        cvt_fused_kernel<<<(n + 255) / 256, blk>>>(wd, wdh, wdl, DMODEL, 0, DMODEL, 2048, n);
        // lm_head
        n = VOCAB * DMODEL / 4;
        cvt_fused_kernel<<<(n + 255) / 256, blk>>>(lmh, lmhh, lmhl, VOCAB, 0, VOCAB, 512, n);
    }

    embed_kernel<<<(N_TOK * DMODEL / 4 + 255) / 256, blk>>>(ids, embed, x);
    rope_table_kernel<<<(SEQ * 64 + 255) / 256, blk>>>(ctab, stab);

    for (int L = 0; L < NLAYER; L++) {
        const __nv_bfloat16* qwh = wqkvh + (size_t)L * QKVD * DMODEL;
        const __nv_bfloat16* qwl = wqkvl + (size_t)L * QKVD * DMODEL;
        const __nv_bfloat16* owh = woh + (size_t)L * DMODEL * DMODEL;
        const __nv_bfloat16* owl = wol + (size_t)L * DMODEL * DMODEL;
        const __nv_bfloat16* guh = wguh + (size_t)L * GUD * DMODEL;
        const __nv_bfloat16* gul = wgul + (size_t)L * GUD * DMODEL;
        const __nv_bfloat16* dwh = wdh + (size_t)L * DMODEL * FFDIM;
        const __nv_bfloat16* dwl = wdl + (size_t)L * DMODEL * FFDIM;
        const float* l1w = ln1 + (size_t)L * DMODEL;
        const float* l2w = ln2 + (size_t)L * DMODEL;

        // attn block
        rmsnorm_bf16_kernel<<<N_TOK, blk>>>(x, l1w, xnh, xnl);
        gemm_mma<<<dim3(N_TOK / BN, QKVD / BM), blk, GEMM_SMEM>>>(xnh, xnl, qwh, qwl, qkv, nullptr, QKVD, DMODEL);
        rope_apply_kernel<<<(N_TOK * NH  * 64 + 255) / 256, blk>>>(qkv,          NH,  QKVD, ctab, stab);
        rope_apply_kernel<<<(N_TOK * NKV * 64 + 255) / 256, blk>>>(qkv + DMODEL, NKV, QKVD, ctab, stab);
        attn_kernel<<<(BATCH * NH * (SEQ / QPW)) * 32 / 256, blk>>>(qkv, ath, atl);
        gemm_mma<<<dim3(N_TOK / BN, DMODEL / BM), blk, GEMM_SMEM>>>(ath, atl, owh, owl, x, x, DMODEL, DMODEL);

        // ffn block
        rmsnorm_bf16_kernel<<<N_TOK, blk>>>(x, l2w, xnh, xnl);
        gemm_mma<<<dim3(N_TOK / BN, GUD / BM), blk, GEMM_SMEM>>>(xnh, xnl, guh, gul, gu, nullptr, GUD, DMODEL);
        silu_mul_bf16_kernel<<<(N_TOK * FFDIM / 4 + 255) / 256, blk>>>(gu, glh, gll);
        gemm_mma<<<dim3(N_TOK / BN, DMODEL / BM), blk, GEMM_SMEM>>>(glh, gll, dwh, dwl, x, x, DMODEL, FFDIM);
    }

    // final norm + lm_head
    rmsnorm_bf16_kernel<<<N_TOK, blk>>>(x, nw, xnh, xnl);
    gemm_mma<<<dim3(N_TOK / BN, VOCAB / BM), blk, GEMM_SMEM>>>(xnh, xnl, lmhh, lmhl, out, nullptr, VOCAB, DMODEL);
}